// round 7
// baseline (speedup 1.0000x reference)
#include <cuda_runtime.h>

#define HWSZ 1444          // 38*38
#define WDIM 38
#define NA   25
#define NB   512
#define NPLANES (NB * NA)  // 12800

// Anchors: base * scale, scales {0.5, 0.75, 1.0, 1.25, 1.5}, matching
// np.concatenate([_BASE * s for s in scales]) in float32.
__constant__ float c_anchors[NA][2] = {
    {1.3221f*0.50f, 1.73145f*0.50f}, {3.19275f*0.50f, 4.00944f*0.50f},
    {5.05587f*0.50f, 8.09892f*0.50f}, {9.47112f*0.50f, 4.84053f*0.50f},
    {11.2364f*0.50f, 10.0071f*0.50f},
    {1.3221f*0.75f, 1.73145f*0.75f}, {3.19275f*0.75f, 4.00944f*0.75f},
    {5.05587f*0.75f, 8.09892f*0.75f}, {9.47112f*0.75f, 4.84053f*0.75f},
    {11.2364f*0.75f, 10.0071f*0.75f},
    {1.3221f*1.00f, 1.73145f*1.00f}, {3.19275f*1.00f, 4.00944f*1.00f},
    {5.05587f*1.00f, 8.09892f*1.00f}, {9.47112f*1.00f, 4.84053f*1.00f},
    {11.2364f*1.00f, 10.0071f*1.00f},
    {1.3221f*1.25f, 1.73145f*1.25f}, {3.19275f*1.25f, 4.00944f*1.25f},
    {5.05587f*1.25f, 8.09892f*1.25f}, {9.47112f*1.25f, 4.84053f*1.25f},
    {11.2364f*1.25f, 10.0071f*1.25f},
    {1.3221f*1.50f, 1.73145f*1.50f}, {3.19275f*1.50f, 4.00944f*1.50f},
    {5.05587f*1.50f, 8.09892f*1.50f}, {9.47112f*1.50f, 4.84053f*1.50f},
    {11.2364f*1.50f, 10.0071f*1.50f}
};

struct BatchInfo {
    float gxm, gxM, gym, gyM;   // gt box edges
    float gw, gh, gwh;          // gt w, h, w*h
    float tx, ty, tw, th;       // target box values at the special cell
    float tconf;                // target conf at the special cell
    int   shw;                  // flat hw of special cell (-1 if not this anchor)
};

__device__ double g_partials[NPLANES];

// ---------------------------------------------------------------------------
// Fused main kernel. One block per (batch, anchor) plane; thread 0 recomputes
// the per-batch metadata (cheap, deterministic, overlapped across blocks).
// Layout: pred[((b*125 + a*5 + comp) * 38 + h) * 38 + w]
// Plane of (b,a) starts at blk*5*1444 floats; comps are +k*1444.
// float4 path: 1444 = 4*361; plane stride 5776 B is 16B-aligned.
// ---------------------------------------------------------------------------
__global__ void __launch_bounds__(256)
k_main(const float* __restrict__ pred, const float* __restrict__ target) {
    int blk = blockIdx.x;
    int b = blk / NA;
    int a = blk - b * NA;

    __shared__ BatchInfo s_bi;

    // ---- per-batch metadata (thread 0 only; precise expf/logf for targets) ----
    if (threadIdx.x == 0) {
        float gx = target[b * 4 + 0] * 38.0f;
        float gy = target[b * 4 + 1] * 38.0f;
        float gw = target[b * 4 + 2] * 38.0f;
        float gh = target[b * 4 + 3] * 38.0f;

        int best = 0;
        float best_iou = -1.0f;
#pragma unroll
        for (int k = 0; k < NA; k++) {
            float aw0 = c_anchors[k][0], ah0 = c_anchors[k][1];
            float inter0 = fminf(aw0, gw) * fminf(ah0, gh);
            float uni0 = aw0 * ah0 + gw * gh - inter0;
            float iou0 = inter0 / uni0;
            if (iou0 > best_iou) { best_iou = iou0; best = k; }
        }

        int gi = (int)gx;
        int gj = (int)gy;
        float baw = c_anchors[best][0], bah = c_anchors[best][1];

        long base = ((long)b * 125 + (long)best * 5) * HWSZ + (long)gj * WDIM + gi;
        float p0 = pred[base];
        float p1 = pred[base + HWSZ];
        float p2 = pred[base + 2 * HWSZ];
        float p3 = pred[base + 3 * HWSZ];

        float bx = 1.0f / (1.0f + expf(-p0)) + (float)gi;
        float by = 1.0f / (1.0f + expf(-p1)) + (float)gj;
        float bw = expf(p2) * baw;
        float bh = expf(p3) * bah;

        float mx = fminf(bx - bw * 0.5f, gx - gw * 0.5f);
        float Mx = fmaxf(bx + bw * 0.5f, gx + gw * 0.5f);
        float my = fminf(by - bh * 0.5f, gy - gh * 0.5f);
        float My = fmaxf(by + bh * 0.5f, gy + gh * 0.5f);
        float cw = bw + gw - (Mx - mx);
        float ch = bh + gh - (My - my);
        float inter = (cw > 0.0f && ch > 0.0f) ? cw * ch : 0.0f;
        float tconf = inter / (bw * bh + gw * gh - inter);

        s_bi.gxm = gx - gw * 0.5f;  s_bi.gxM = gx + gw * 0.5f;
        s_bi.gym = gy - gh * 0.5f;  s_bi.gyM = gy + gh * 0.5f;
        s_bi.gw = gw; s_bi.gh = gh; s_bi.gwh = gw * gh;
        s_bi.tx = gx - (float)gi;
        s_bi.ty = gy - (float)gj;
        s_bi.tw = logf(gw / baw);
        s_bi.th = logf(gh / bah);
        s_bi.tconf = tconf;
        s_bi.shw = (a == best) ? (gj * WDIM + gi) : -1;
    }

    // ---- issue all plane loads up front (independent of metadata) ----
    const float4* p = reinterpret_cast<const float4*>(pred + (size_t)blk * 5 * HWSZ);

    int q0 = threadIdx.x;            // always < 361 (blockDim 256)
    int q1 = q0 + 256;
    bool has1 = (q1 < 361);

    float4 v0x = p[q0];
    float4 v0y = p[q0 + 361];
    float4 v0w = p[q0 + 722];
    float4 v0h = p[q0 + 1083];
    float4 v0c = p[q0 + 1444];

    float4 v1x, v1y, v1w, v1h, v1c;
    if (has1) {
        v1x = p[q1];
        v1y = p[q1 + 361];
        v1w = p[q1 + 722];
        v1h = p[q1 + 1083];
        v1c = p[q1 + 1444];
    }

    __syncthreads();
    BatchInfo bi = s_bi;
    float aw = c_anchors[a][0], ah = c_anchors[a][1];
    int shw = bi.shw;

    float acc = 0.0f;

    auto cell = [&](float tx, float ty, float tw, float th, float tc, int hw) {
        int h = hw / WDIM;
        int w = hw - h * WDIM;

        float sx = __fdividef(1.0f, 1.0f + __expf(-tx));
        float sy = __fdividef(1.0f, 1.0f + __expf(-ty));
        float pc = __fdividef(1.0f, 1.0f + __expf(-tc));
        float bw = __expf(tw) * aw;
        float bh = __expf(th) * ah;

        float bx = sx + (float)w;
        float by = sy + (float)h;
        float hbw = 0.5f * bw, hbh = 0.5f * bh;

        float mx = fminf(bx - hbw, bi.gxm);
        float Mx = fmaxf(bx + hbw, bi.gxM);
        float my = fminf(by - hbh, bi.gym);
        float My = fmaxf(by + hbh, bi.gyM);
        float cw = bi.gw + bw - (Mx - mx);
        float ch = bi.gh + bh - (My - my);
        float inter = (cw > 0.0f && ch > 0.0f) ? cw * ch : 0.0f;
        float uni = bw * bh + bi.gwh - inter;

        bool sp = (hw == shw);
        float txt = sp ? bi.tx : 0.5f;
        float tyt = sp ? bi.ty : 0.5f;
        float twt = sp ? bi.tw : 0.0f;
        float tht = sp ? bi.th : 0.0f;
        float tct = sp ? bi.tconf : 0.0f;
        // conf_mask^2: 5 at special cell, else 0 if iou>0.6 else 1.
        // iou > 0.6  <=>  inter > 0.6*union (union > 0 always).
        float cm2 = sp ? 5.0f : ((inter > 0.6f * uni) ? 0.0f : 1.0f);

        float dx = sx - txt;
        float dy = sy - tyt;
        float dw = tw - twt;
        float dh = th - tht;
        float dc = pc - tct;

        acc += dx * dx + dy * dy + dw * dw + dh * dh + cm2 * (dc * dc);
    };

    {
        int hw0 = q0 * 4;
        cell(v0x.x, v0y.x, v0w.x, v0h.x, v0c.x, hw0 + 0);
        cell(v0x.y, v0y.y, v0w.y, v0h.y, v0c.y, hw0 + 1);
        cell(v0x.z, v0y.z, v0w.z, v0h.z, v0c.z, hw0 + 2);
        cell(v0x.w, v0y.w, v0w.w, v0h.w, v0c.w, hw0 + 3);
    }
    if (has1) {
        int hw1 = q1 * 4;
        cell(v1x.x, v1y.x, v1w.x, v1h.x, v1c.x, hw1 + 0);
        cell(v1x.y, v1y.y, v1w.y, v1h.y, v1c.y, hw1 + 1);
        cell(v1x.z, v1y.z, v1w.z, v1h.z, v1c.z, hw1 + 2);
        cell(v1x.w, v1y.w, v1w.w, v1h.w, v1c.w, hw1 + 3);
    }

    // block reduction: warp shuffle (fp32), then 8 warp sums -> double partial
    for (int o = 16; o; o >>= 1) acc += __shfl_xor_sync(0xffffffffu, acc, o);
    __shared__ float warp_s[8];
    int lane = threadIdx.x & 31;
    int wid = threadIdx.x >> 5;
    if (lane == 0) warp_s[wid] = acc;
    __syncthreads();
    if (threadIdx.x == 0) {
        double s = 0.0;
#pragma unroll
        for (int i = 0; i < 8; i++) s += (double)warp_s[i];
        g_partials[blk] = s;
    }
}

// ---------------------------------------------------------------------------
// Final deterministic reduction of 12800 double partials.
// ---------------------------------------------------------------------------
__global__ void k_final(float* __restrict__ out) {
    double s = 0.0;
    for (int i = threadIdx.x; i < NPLANES; i += 1024) s += g_partials[i];
    for (int o = 16; o; o >>= 1) s += __shfl_xor_sync(0xffffffffu, s, o);
    __shared__ double ws[32];
    int lane = threadIdx.x & 31;
    int wid = threadIdx.x >> 5;
    if (lane == 0) ws[wid] = s;
    __syncthreads();
    if (threadIdx.x == 0) {
        double t = 0.0;
#pragma unroll
        for (int i = 0; i < 32; i++) t += ws[i];
        out[0] = (float)(0.5 * t);
    }
}

extern "C" void kernel_launch(void* const* d_in, const int* in_sizes, int n_in,
                              void* d_out, int out_size) {
    const float* pred = (const float*)d_in[0];
    const float* target = (const float*)d_in[1];
    float* out = (float*)d_out;

    k_main<<<NPLANES, 256>>>(pred, target);
    k_final<<<1, 1024>>>(out);
}

// round 8
// speedup vs baseline: 1.1678x; 1.1678x over previous
#include <cuda_runtime.h>

#define HWSZ 1444          // 38*38
#define WDIM 38
#define NA   25
#define NB   512
#define NPLANES (NB * NA)  // 12800

// Anchors: base * scale, scales {0.5, 0.75, 1.0, 1.25, 1.5}, matching
// np.concatenate([_BASE * s for s in scales]) in float32.
__constant__ float c_anchors[NA][2] = {
    {1.3221f*0.50f, 1.73145f*0.50f}, {3.19275f*0.50f, 4.00944f*0.50f},
    {5.05587f*0.50f, 8.09892f*0.50f}, {9.47112f*0.50f, 4.84053f*0.50f},
    {11.2364f*0.50f, 10.0071f*0.50f},
    {1.3221f*0.75f, 1.73145f*0.75f}, {3.19275f*0.75f, 4.00944f*0.75f},
    {5.05587f*0.75f, 8.09892f*0.75f}, {9.47112f*0.75f, 4.84053f*0.75f},
    {11.2364f*0.75f, 10.0071f*0.75f},
    {1.3221f*1.00f, 1.73145f*1.00f}, {3.19275f*1.00f, 4.00944f*1.00f},
    {5.05587f*1.00f, 8.09892f*1.00f}, {9.47112f*1.00f, 4.84053f*1.00f},
    {11.2364f*1.00f, 10.0071f*1.00f},
    {1.3221f*1.25f, 1.73145f*1.25f}, {3.19275f*1.25f, 4.00944f*1.25f},
    {5.05587f*1.25f, 8.09892f*1.25f}, {9.47112f*1.25f, 4.84053f*1.25f},
    {11.2364f*1.25f, 10.0071f*1.25f},
    {1.3221f*1.50f, 1.73145f*1.50f}, {3.19275f*1.50f, 4.00944f*1.50f},
    {5.05587f*1.50f, 8.09892f*1.50f}, {9.47112f*1.50f, 4.84053f*1.50f},
    {11.2364f*1.50f, 10.0071f*1.50f}
};

struct BatchInfo {
    float gxm, gxM, gym, gyM;   // gt box edges
    float gw, gh, gwh;          // gt w, h, w*h
    float tx, ty, tw, th;       // target box values at the special cell
    float tconf;                // target conf at the special cell
    int   best, shw;            // best anchor, flat hw index of special cell
};

__device__ BatchInfo g_binfo[NB];
__device__ float     g_partials[NPLANES];

// ---------------------------------------------------------------------------
// Kernel 1: per-batch metadata. One block per batch (lane 0 works) so the
// latency chains of all 512 batches overlap across SMs.
// ---------------------------------------------------------------------------
__global__ void k_batch_meta(const float* __restrict__ pred,
                             const float* __restrict__ target) {
    if (threadIdx.x != 0) return;
    int b = blockIdx.x;

    float4 t4 = reinterpret_cast<const float4*>(target)[b];
    float gx = t4.x * 38.0f;
    float gy = t4.y * 38.0f;
    float gw = t4.z * 38.0f;
    float gh = t4.w * 38.0f;

    // argmax over anchor IoU (boxes centered at origin):
    // inter = min(aw,gw)*min(ah,gh); union = aw*ah + gw*gh - inter
    int best = 0;
    float best_iou = -1.0f;
#pragma unroll
    for (int a = 0; a < NA; a++) {
        float aw = c_anchors[a][0], ah = c_anchors[a][1];
        float inter = fminf(aw, gw) * fminf(ah, gh);
        float uni = aw * ah + gw * gh - inter;
        float iou = inter / uni;
        if (iou > best_iou) { best_iou = iou; best = a; }
    }

    int gi = (int)gx;
    int gj = (int)gy;
    float aw = c_anchors[best][0], ah = c_anchors[best][1];

    // pred box at the special cell (b, best, :, gj, gi) — 4 independent loads
    long base = ((long)b * 125 + (long)best * 5) * HWSZ + (long)gj * WDIM + gi;
    float p0 = pred[base];
    float p1 = pred[base + HWSZ];
    float p2 = pred[base + 2 * HWSZ];
    float p3 = pred[base + 3 * HWSZ];

    float bx = 1.0f / (1.0f + expf(-p0)) + (float)gi;
    float by = 1.0f / (1.0f + expf(-p1)) + (float)gj;
    float bw = expf(p2) * aw;
    float bh = expf(p3) * ah;

    float mx = fminf(bx - bw * 0.5f, gx - gw * 0.5f);
    float Mx = fmaxf(bx + bw * 0.5f, gx + gw * 0.5f);
    float my = fminf(by - bh * 0.5f, gy - gh * 0.5f);
    float My = fmaxf(by + bh * 0.5f, gy + gh * 0.5f);
    float cw = bw + gw - (Mx - mx);
    float ch = bh + gh - (My - my);
    float inter = (cw > 0.0f && ch > 0.0f) ? cw * ch : 0.0f;
    float tconf = inter / (bw * bh + gw * gh - inter);

    BatchInfo s;
    s.gxm = gx - gw * 0.5f;  s.gxM = gx + gw * 0.5f;
    s.gym = gy - gh * 0.5f;  s.gyM = gy + gh * 0.5f;
    s.gw = gw; s.gh = gh; s.gwh = gw * gh;
    s.tx = gx - (float)gi;
    s.ty = gy - (float)gj;
    s.tw = logf(gw / aw);
    s.th = logf(gh / ah);
    s.tconf = tconf;
    s.best = best;
    s.shw = gj * WDIM + gi;
    g_binfo[b] = s;
}

// ---------------------------------------------------------------------------
// Kernel 2: fused main loss pass. One block per (batch, anchor) plane.
// Layout: pred[((b*125 + a*5 + comp) * 38 + h) * 38 + w]
// Plane of (b,a) starts at blk*5*1444 floats; comps are +k*1444.
// float4 path: 1444 = 4*361; plane stride 5776 B is 16B-aligned.
// ---------------------------------------------------------------------------
__global__ void __launch_bounds__(256)
k_main(const float* __restrict__ pred) {
    int blk = blockIdx.x;
    int b = blk / NA;
    int a = blk - b * NA;

    BatchInfo bi = g_binfo[b];
    float aw = c_anchors[a][0], ah = c_anchors[a][1];
    int shw = (a == bi.best) ? bi.shw : -1;  // special cell only on best anchor

    const float4* p = reinterpret_cast<const float4*>(pred + (size_t)blk * 5 * HWSZ);

    float acc = 0.0f;
    for (int q = threadIdx.x; q < 361; q += 256) {
        float4 vx = p[q];
        float4 vy = p[q + 361];
        float4 vw = p[q + 722];
        float4 vh = p[q + 1083];
        float4 vc = p[q + 1444];

        float ax[4] = {vx.x, vx.y, vx.z, vx.w};
        float ay[4] = {vy.x, vy.y, vy.z, vy.w};
        float aww[4] = {vw.x, vw.y, vw.z, vw.w};
        float ahh[4] = {vh.x, vh.y, vh.z, vh.w};
        float ac[4] = {vc.x, vc.y, vc.z, vc.w};

        int hw0 = q * 4;
#pragma unroll
        for (int j = 0; j < 4; j++) {
            int hw = hw0 + j;
            int h = hw / WDIM;
            int w = hw - h * WDIM;

            float tx = ax[j], ty = ay[j], tw = aww[j], th = ahh[j], tc = ac[j];

            float sx = __fdividef(1.0f, 1.0f + __expf(-tx));
            float sy = __fdividef(1.0f, 1.0f + __expf(-ty));
            float pc = __fdividef(1.0f, 1.0f + __expf(-tc));
            float bw = __expf(tw) * aw;
            float bh = __expf(th) * ah;

            float bx = sx + (float)w;
            float by = sy + (float)h;
            float hbw = 0.5f * bw, hbh = 0.5f * bh;

            float mx = fminf(bx - hbw, bi.gxm);
            float Mx = fmaxf(bx + hbw, bi.gxM);
            float my = fminf(by - hbh, bi.gym);
            float My = fmaxf(by + hbh, bi.gyM);
            float cw = bi.gw + bw - (Mx - mx);
            float ch = bi.gh + bh - (My - my);
            float inter = (cw > 0.0f && ch > 0.0f) ? cw * ch : 0.0f;
            float uni = bw * bh + bi.gwh - inter;

            bool sp = (hw == shw);
            float txt = sp ? bi.tx : 0.5f;
            float tyt = sp ? bi.ty : 0.5f;
            float twt = sp ? bi.tw : 0.0f;
            float tht = sp ? bi.th : 0.0f;
            float tct = sp ? bi.tconf : 0.0f;
            // conf_mask^2: 5 at special cell, else 0 if iou>0.6 else 1.
            // iou > 0.6  <=>  inter > 0.6*union (union > 0 always).
            float cm2 = sp ? 5.0f : ((inter > 0.6f * uni) ? 0.0f : 1.0f);

            float dx = sx - txt;
            float dy = sy - tyt;
            float dw = tw - twt;
            float dh = th - tht;
            float dc = pc - tct;

            acc += dx * dx + dy * dy + dw * dw + dh * dh + cm2 * (dc * dc);
        }
    }

    // block reduction: warp shuffle (fp32), then 8 warp sums -> float partial
    for (int o = 16; o; o >>= 1) acc += __shfl_xor_sync(0xffffffffu, acc, o);
    __shared__ float warp_s[8];
    int lane = threadIdx.x & 31;
    int wid = threadIdx.x >> 5;
    if (lane == 0) warp_s[wid] = acc;
    __syncthreads();
    if (threadIdx.x == 0) {
        double s = 0.0;
#pragma unroll
        for (int i = 0; i < 8; i++) s += (double)warp_s[i];
        g_partials[blk] = (float)s;
    }
}

// ---------------------------------------------------------------------------
// Kernel 3: final deterministic reduction of 12800 float partials (L2-hot).
// float4 loads, independent per thread -> one L2 latency round.
// ---------------------------------------------------------------------------
__global__ void k_final(float* __restrict__ out) {
    const float4* p4 = reinterpret_cast<const float4*>(g_partials);  // 3200 float4
    int t = threadIdx.x;  // 1024 threads

    float4 a0 = p4[t];
    float4 a1 = p4[t + 1024];
    float4 a2 = p4[t + 2048];
    float4 a3 = (t < 128) ? p4[t + 3072] : make_float4(0.f, 0.f, 0.f, 0.f);

    double s = ((double)a0.x + (double)a0.y) + ((double)a0.z + (double)a0.w);
    s += ((double)a1.x + (double)a1.y) + ((double)a1.z + (double)a1.w);
    s += ((double)a2.x + (double)a2.y) + ((double)a2.z + (double)a2.w);
    s += ((double)a3.x + (double)a3.y) + ((double)a3.z + (double)a3.w);

    for (int o = 16; o; o >>= 1) s += __shfl_xor_sync(0xffffffffu, s, o);
    __shared__ double ws[32];
    int lane = t & 31;
    int wid = t >> 5;
    if (lane == 0) ws[wid] = s;
    __syncthreads();
    if (t == 0) {
        double tt = 0.0;
#pragma unroll
        for (int i = 0; i < 32; i++) tt += ws[i];
        out[0] = (float)(0.5 * tt);
    }
}

extern "C" void kernel_launch(void* const* d_in, const int* in_sizes, int n_in,
                              void* d_out, int out_size) {
    const float* pred = (const float*)d_in[0];
    const float* target = (const float*)d_in[1];
    float* out = (float*)d_out;

    k_batch_meta<<<NB, 32>>>(pred, target);
    k_main<<<NPLANES, 256>>>(pred);
    k_final<<<1, 1024>>>(out);
}

// round 9
// speedup vs baseline: 1.3769x; 1.1790x over previous
#include <cuda_runtime.h>

#define HWSZ 1444          // 38*38
#define WDIM 38
#define NA   25
#define NB   512
#define NPLANES (NB * NA)  // 12800

// Anchors: base * scale, scales {0.5, 0.75, 1.0, 1.25, 1.5}, matching
// np.concatenate([_BASE * s for s in scales]) in float32.
__constant__ float c_anchors[NA][2] = {
    {1.3221f*0.50f, 1.73145f*0.50f}, {3.19275f*0.50f, 4.00944f*0.50f},
    {5.05587f*0.50f, 8.09892f*0.50f}, {9.47112f*0.50f, 4.84053f*0.50f},
    {11.2364f*0.50f, 10.0071f*0.50f},
    {1.3221f*0.75f, 1.73145f*0.75f}, {3.19275f*0.75f, 4.00944f*0.75f},
    {5.05587f*0.75f, 8.09892f*0.75f}, {9.47112f*0.75f, 4.84053f*0.75f},
    {11.2364f*0.75f, 10.0071f*0.75f},
    {1.3221f*1.00f, 1.73145f*1.00f}, {3.19275f*1.00f, 4.00944f*1.00f},
    {5.05587f*1.00f, 8.09892f*1.00f}, {9.47112f*1.00f, 4.84053f*1.00f},
    {11.2364f*1.00f, 10.0071f*1.00f},
    {1.3221f*1.25f, 1.73145f*1.25f}, {3.19275f*1.25f, 4.00944f*1.25f},
    {5.05587f*1.25f, 8.09892f*1.25f}, {9.47112f*1.25f, 4.84053f*1.25f},
    {11.2364f*1.25f, 10.0071f*1.25f},
    {1.3221f*1.50f, 1.73145f*1.50f}, {3.19275f*1.50f, 4.00944f*1.50f},
    {5.05587f*1.50f, 8.09892f*1.50f}, {9.47112f*1.50f, 4.84053f*1.50f},
    {11.2364f*1.50f, 10.0071f*1.50f}
};

__device__ float g_partials[NPLANES];

struct GT { float gxm, gxM, gym, gyM, gw, gh, gwh; };

__device__ __forceinline__ GT make_gt(float4 t4) {
    GT g;
    float gx = t4.x * 38.0f, gy = t4.y * 38.0f;
    g.gw = t4.z * 38.0f;  g.gh = t4.w * 38.0f;
    g.gxm = gx - g.gw * 0.5f;  g.gxM = gx + g.gw * 0.5f;
    g.gym = gy - g.gh * 0.5f;  g.gyM = gy + g.gh * 0.5f;
    g.gwh = g.gw * g.gh;
    return g;
}

__device__ __forceinline__ float sigmoid_fast(float x) {
    return __fdividef(1.0f, 1.0f + __expf(-x));
}

// Generic (non-special) cell loss contribution. Used identically in k_main and
// in k_final's correction so the special-cell generic term cancels.
__device__ __forceinline__ float cell_generic(
    float px, float py, float pw, float ph, float pcin,
    float wf, float hf, float aw, float ah, const GT& g)
{
    float sx = sigmoid_fast(px);
    float sy = sigmoid_fast(py);
    float pc = sigmoid_fast(pcin);
    float bw = __expf(pw) * aw;
    float bh = __expf(ph) * ah;

    float bx = sx + wf;
    float by = sy + hf;
    float hbw = 0.5f * bw, hbh = 0.5f * bh;

    float mx = fminf(bx - hbw, g.gxm);
    float Mx = fmaxf(bx + hbw, g.gxM);
    float my = fminf(by - hbh, g.gym);
    float My = fmaxf(by + hbh, g.gyM);
    float cw = g.gw + bw - (Mx - mx);
    float ch = g.gh + bh - (My - my);
    float inter = (cw > 0.0f && ch > 0.0f) ? cw * ch : 0.0f;
    float uni = bw * bh + g.gwh - inter;

    // conf_mask^2: 0 if iou > 0.6 else 1.  iou>0.6 <=> inter>0.6*uni (uni>0).
    float cm2 = (inter > 0.6f * uni) ? 0.0f : 1.0f;

    float dx = sx - 0.5f;
    float dy = sy - 0.5f;
    return dx * dx + dy * dy + pw * pw + ph * ph + cm2 * (pc * pc);
}

// ---------------------------------------------------------------------------
// Main pass: one block per (batch, anchor) plane, ALL cells treated generic.
// No dependency on any prior kernel. Special-cell fix happens in k_final.
// Layout: pred[((b*125 + a*5 + comp) * 38 + h) * 38 + w]
// float4 path: 1444 = 4*361; plane stride 5776 B is 16B-aligned.
// ---------------------------------------------------------------------------
__global__ void __launch_bounds__(384)
k_main(const float* __restrict__ pred, const float* __restrict__ target) {
    int blk = blockIdx.x;
    int b = blk / NA;
    int a = blk - b * NA;

    GT g = make_gt(__ldg(&reinterpret_cast<const float4*>(target)[b]));
    float aw = c_anchors[a][0], ah = c_anchors[a][1];

    const float4* p = reinterpret_cast<const float4*>(pred + (size_t)blk * 5 * HWSZ);

    float acc = 0.0f;
    int q = threadIdx.x;
    if (q < 361) {
        float4 vx = p[q];
        float4 vy = p[q + 361];
        float4 vw = p[q + 722];
        float4 vh = p[q + 1083];
        float4 vc = p[q + 1444];

        float ax[4]  = {vx.x, vx.y, vx.z, vx.w};
        float ay[4]  = {vy.x, vy.y, vy.z, vy.w};
        float aww[4] = {vw.x, vw.y, vw.z, vw.w};
        float ahh[4] = {vh.x, vh.y, vh.z, vh.w};
        float ac[4]  = {vc.x, vc.y, vc.z, vc.w};

        int hw0 = q * 4;
#pragma unroll
        for (int j = 0; j < 4; j++) {
            int hw = hw0 + j;
            int h = hw / WDIM;
            int w = hw - h * WDIM;
            acc += cell_generic(ax[j], ay[j], aww[j], ahh[j], ac[j],
                                (float)w, (float)h, aw, ah, g);
        }
    }

    // block reduction: warp shuffle, then 12 warp sums
    for (int o = 16; o; o >>= 1) acc += __shfl_xor_sync(0xffffffffu, acc, o);
    __shared__ float warp_s[12];
    int lane = threadIdx.x & 31;
    int wid = threadIdx.x >> 5;
    if (lane == 0) warp_s[wid] = acc;
    __syncthreads();
    if (threadIdx.x == 0) {
        float s = 0.0f;
#pragma unroll
        for (int i = 0; i < 12; i++) s += warp_s[i];
        g_partials[blk] = s;
    }
}

// ---------------------------------------------------------------------------
// Final reduction + per-batch special-cell correction.
// Threads 0..511 each handle one batch: recompute meta, gather 5 pred values
// at the special cell, delta = special_contrib - generic_contrib.
// All 1024 threads also sum the 12800 float partials (L2-hot, float4 loads).
// ---------------------------------------------------------------------------
__global__ void k_final(const float* __restrict__ pred,
                        const float* __restrict__ target,
                        float* __restrict__ out) {
    int t = threadIdx.x;  // 1024 threads

    const float4* p4 = reinterpret_cast<const float4*>(g_partials);  // 3200 float4
    float4 a0 = p4[t];
    float4 a1 = p4[t + 1024];
    float4 a2 = p4[t + 2048];
    float4 a3 = (t < 128) ? p4[t + 3072] : make_float4(0.f, 0.f, 0.f, 0.f);

    double s = ((double)a0.x + (double)a0.y) + ((double)a0.z + (double)a0.w);
    s += ((double)a1.x + (double)a1.y) + ((double)a1.z + (double)a1.w);
    s += ((double)a2.x + (double)a2.y) + ((double)a2.z + (double)a2.w);
    s += ((double)a3.x + (double)a3.y) + ((double)a3.z + (double)a3.w);

    if (t < NB) {
        int b = t;
        float4 t4 = __ldg(&reinterpret_cast<const float4*>(target)[b]);
        float gx = t4.x * 38.0f;
        float gy = t4.y * 38.0f;
        float gw = t4.z * 38.0f;
        float gh = t4.w * 38.0f;

        // argmax over anchor IoU (origin-centered boxes); '>' keeps first.
        int best = 0;
        float best_iou = -1.0f;
#pragma unroll
        for (int k = 0; k < NA; k++) {
            float aw0 = c_anchors[k][0], ah0 = c_anchors[k][1];
            float inter0 = fminf(aw0, gw) * fminf(ah0, gh);
            float uni0 = aw0 * ah0 + gw * gh - inter0;
            float iou0 = inter0 / uni0;
            if (iou0 > best_iou) { best_iou = iou0; best = k; }
        }

        int gi = (int)gx;
        int gj = (int)gy;
        float aw = c_anchors[best][0], ah = c_anchors[best][1];

        // 5 pred values at the special cell (b, best, :, gj, gi)
        long base = ((long)b * 125 + (long)best * 5) * HWSZ + (long)gj * WDIM + gi;
        float p0 = __ldg(pred + base);
        float p1 = __ldg(pred + base + HWSZ);
        float p2 = __ldg(pred + base + 2 * HWSZ);
        float p3 = __ldg(pred + base + 3 * HWSZ);
        float pcv = __ldg(pred + base + 4 * HWSZ);

        // generic contribution this cell already received in k_main (same math)
        GT g = make_gt(t4);
        float gen = cell_generic(p0, p1, p2, p3, pcv,
                                 (float)gi, (float)gj, aw, ah, g);

        // special contribution (targets computed with precise expf/logf)
        float sx = sigmoid_fast(p0);
        float sy = sigmoid_fast(p1);
        float pc = sigmoid_fast(pcv);

        float bx = 1.0f / (1.0f + expf(-p0)) + (float)gi;
        float by = 1.0f / (1.0f + expf(-p1)) + (float)gj;
        float bw = expf(p2) * aw;
        float bh = expf(p3) * ah;
        float mx = fminf(bx - bw * 0.5f, gx - gw * 0.5f);
        float Mx = fmaxf(bx + bw * 0.5f, gx + gw * 0.5f);
        float my = fminf(by - bh * 0.5f, gy - gh * 0.5f);
        float My = fmaxf(by + bh * 0.5f, gy + gh * 0.5f);
        float cw = bw + gw - (Mx - mx);
        float ch = bh + gh - (My - my);
        float inter = (cw > 0.0f && ch > 0.0f) ? cw * ch : 0.0f;
        float tconf = inter / (bw * bh + gw * gh - inter);

        float txs = gx - (float)gi;
        float tys = gy - (float)gj;
        float twt = logf(gw / aw);
        float tht = logf(gh / ah);

        float ddx = sx - txs;
        float ddy = sy - tys;
        float ddw = p2 - twt;
        float ddh = p3 - tht;
        float ddc = pc - tconf;
        float sp = ddx * ddx + ddy * ddy + ddw * ddw + ddh * ddh
                 + 5.0f * (ddc * ddc);

        s += (double)(sp - gen);
    }

    for (int o = 16; o; o >>= 1) s += __shfl_xor_sync(0xffffffffu, s, o);
    __shared__ double ws[32];
    int lane = t & 31;
    int wid = t >> 5;
    if (lane == 0) ws[wid] = s;
    __syncthreads();
    if (t == 0) {
        double tt = 0.0;
#pragma unroll
        for (int i = 0; i < 32; i++) tt += ws[i];
        out[0] = (float)(0.5 * tt);
    }
}

extern "C" void kernel_launch(void* const* d_in, const int* in_sizes, int n_in,
                              void* d_out, int out_size) {
    const float* pred = (const float*)d_in[0];
    const float* target = (const float*)d_in[1];
    float* out = (float*)d_out;

    k_main<<<NPLANES, 384>>>(pred, target);
    k_final<<<1, 1024>>>(pred, target, out);
}